// round 3
// baseline (speedup 1.0000x reference)
#include <cuda_runtime.h>
#include <cuda_bf16.h>

// Problem constants (fixed by the reference):
//   B=128, W=256, H=256, MAX_OBJS=128  -> 16384 boxes total
// Inputs (metadata order):
//   d_in[0] loc_pred  f32 [128,256,256,4]
//   d_in[1] loc_true  f32 [128,128,4]
//   d_in[2] reg_mask  f32 [128,128]
//   d_in[3] indices   i32 [128,128,3]
// Output: f32 scalar.

#define NB   16     // blocks
#define NT   256    // threads per block
#define KPT  4      // boxes per thread  (NB*NT*KPT = 16384)

__device__ float        g_part_loss[NB];
__device__ float        g_part_mask[NB];
__device__ unsigned int g_done = 0;

__device__ __forceinline__ float giou_term(
    float b1y0, float b1x0, float b1y1, float b1x1,
    float b2y0, float b2x0, float b2y1, float b2x1, float m)
{
    const float a1 = fmaxf(b1y1 - b1y0, 0.0f) * fmaxf(b1x1 - b1x0, 0.0f);
    const float a2 = fmaxf(b2y1 - b2y0, 0.0f) * fmaxf(b2x1 - b2x0, 0.0f);

    const float iy = fmaxf(fminf(b1y1, b2y1) - fmaxf(b1y0, b2y0), 0.0f);
    const float ix = fmaxf(fminf(b1x1, b2x1) - fmaxf(b1x0, b2x0), 0.0f);
    const float inter = iy * ix;
    const float uni   = a1 + a2 - inter;
    const float iou   = (uni != 0.0f) ? (inter / uni) : 0.0f;

    const float ey = fmaxf(fmaxf(b1y1, b2y1) - fminf(b1y0, b2y0), 0.0f);
    const float ex = fmaxf(fmaxf(b1x1, b2x1) - fminf(b1x0, b2x0), 0.0f);
    const float enc  = ey * ex;
    const float giou = iou - ((enc != 0.0f) ? ((enc - uni) / enc) : 0.0f);
    return (1.0f - giou) * m;
}

__global__ void __launch_bounds__(NT) giou_loss_kernel(
    const float* __restrict__ loc_pred,
    const float* __restrict__ loc_true,
    const float* __restrict__ reg_mask,
    const int*   __restrict__ indices,
    float*       __restrict__ out)
{
    const int g = blockIdx.x * NT + threadIdx.x;    // thread's group id
    const size_t box0 = (size_t)g * KPT;            // first of 4 boxes

    // ---- issue ALL independent loads up front (max MLP) ----
    // indices for 4 boxes = 12 ints = 3 x int4 (48B, 16B-aligned).
    const int4* ivec = reinterpret_cast<const int4*>(indices + box0 * 3);
    const int4 i0 = ivec[0];   // b0 p0 z0 b1
    const int4 i1 = ivec[1];   // p1 z1 b2 p2
    const int4 i2 = ivec[2];   // z2 b3 p3 z3

    const float4* tvec = reinterpret_cast<const float4*>(loc_true + box0 * 4);
    const float4 t0 = tvec[0];
    const float4 t1 = tvec[1];
    const float4 t2 = tvec[2];
    const float4 t3 = tvec[3];

    const float4 mv = *reinterpret_cast<const float4*>(reg_mask + box0);

    // ---- 4 independent dependent gathers ----
    const int b0 = i0.x, p0 = i0.y;
    const int b1 = i0.w, p1 = i1.x;
    const int b2 = i1.z, p2 = i1.w;
    const int b3 = i2.y, p3 = i2.z;

    const float4 q0 = *reinterpret_cast<const float4*>(loc_pred + (((size_t)b0 << 16) + (size_t)p0) * 4);
    const float4 q1 = *reinterpret_cast<const float4*>(loc_pred + (((size_t)b1 << 16) + (size_t)p1) * 4);
    const float4 q2 = *reinterpret_cast<const float4*>(loc_pred + (((size_t)b2 << 16) + (size_t)p2) * 4);
    const float4 q3 = *reinterpret_cast<const float4*>(loc_pred + (((size_t)b3 << 16) + (size_t)p3) * 4);

    const float inv = 1.0f / 256.0f;
    float loss = 0.0f;
    loss += giou_term(q0.x*inv, q0.y*inv, q0.z*inv, q0.w*inv, t0.x, t0.y, t0.z, t0.w, mv.x);
    loss += giou_term(q1.x*inv, q1.y*inv, q1.z*inv, q1.w*inv, t1.x, t1.y, t1.z, t1.w, mv.y);
    loss += giou_term(q2.x*inv, q2.y*inv, q2.z*inv, q2.w*inv, t2.x, t2.y, t2.z, t2.w, mv.z);
    loss += giou_term(q3.x*inv, q3.y*inv, q3.z*inv, q3.w*inv, t3.x, t3.y, t3.z, t3.w, mv.w);
    float mask = mv.x + mv.y + mv.z + mv.w;

    // ---- block reduction: 8 warps ----
    #pragma unroll
    for (int off = 16; off > 0; off >>= 1) {
        loss += __shfl_down_sync(0xFFFFFFFFu, loss, off);
        mask += __shfl_down_sync(0xFFFFFFFFu, mask, off);
    }
    __shared__ float s_loss[8], s_mask[8];
    const int lane = threadIdx.x & 31;
    const int warp = threadIdx.x >> 5;
    if (lane == 0) { s_loss[warp] = loss; s_mask[warp] = mask; }
    __syncthreads();

    if (threadIdx.x == 0) {
        float bl = 0.0f, bm = 0.0f;
        #pragma unroll
        for (int w = 0; w < 8; w++) { bl += s_loss[w]; bm += s_mask[w]; }

        // publish partials with plain stores (no RMW contention)
        g_part_loss[blockIdx.x] = bl;
        g_part_mask[blockIdx.x] = bm;
        __threadfence();
        const unsigned ticket = atomicAdd(&g_done, 1u);
        if (ticket == (unsigned)(NB - 1)) {
            __threadfence();   // acquire: partials of all blocks visible
            volatile float* vl = g_part_loss;
            volatile float* vm = g_part_mask;
            float L = 0.0f, M = 0.0f;
            #pragma unroll
            for (int k = 0; k < NB; k++) { L += vl[k]; M += vm[k]; }
            g_done = 0;        // reset for next graph replay
            out[0] = L / M;
        }
    }
}

extern "C" void kernel_launch(void* const* d_in, const int* in_sizes, int n_in,
                              void* d_out, int out_size)
{
    const float* loc_pred = (const float*)d_in[0];
    const float* loc_true = (const float*)d_in[1];
    const float* reg_mask = (const float*)d_in[2];
    const int*   indices  = (const int*)  d_in[3];
    float*       out      = (float*)d_out;
    (void)in_sizes; (void)n_in; (void)out_size;

    giou_loss_kernel<<<NB, NT>>>(loc_pred, loc_true, reg_mask, indices, out);
}

// round 5
// speedup vs baseline: 1.1012x; 1.1012x over previous
#include <cuda_runtime.h>
#include <cuda_bf16.h>

// Problem constants (fixed by the reference):
//   B=128, W=256, H=256, MAX_OBJS=128  -> 16384 boxes
// Inputs (metadata order):
//   d_in[0] loc_pred  f32 [128,256,256,4]
//   d_in[1] loc_true  f32 [128,128,4]
//   d_in[2] reg_mask  f32 [128,128]
//   d_in[3] indices   i32 [128,128,3]
// Output: f32 scalar.

#define NB 128   // blocks  (one wave across the chip: max SM-level MLP)
#define NT 128   // threads

__device__ float2       g_part[NB];   // (loss, mask) per block
__device__ unsigned int g_done = 0;

__global__ void __launch_bounds__(NT) giou_loss_kernel(
    const float* __restrict__ loc_pred,
    const float* __restrict__ loc_true,
    const float* __restrict__ reg_mask,
    const int*   __restrict__ indices,
    float*       __restrict__ out)
{
    const int i = blockIdx.x * NT + threadIdx.x;   // box index in [0, 16384)

    // ---- independent loads first (overlap DRAM latency) ----
    const int bidx = __ldg(indices + (size_t)i * 3 + 0);
    const int pos  = __ldg(indices + (size_t)i * 3 + 1);
    const float4 t = *reinterpret_cast<const float4*>(loc_true + (size_t)i * 4);
    const float  m = __ldg(reg_mask + i);

    // ---- dependent gather: predicted box, normalize by 256 ----
    const float4 p = *reinterpret_cast<const float4*>(
        loc_pred + (((size_t)bidx << 16) + (size_t)pos) * 4);
    const float inv = 1.0f / 256.0f;
    const float b1y0 = p.x * inv, b1x0 = p.y * inv;
    const float b1y1 = p.z * inv, b1x1 = p.w * inv;
    const float b2y0 = t.x, b2x0 = t.y, b2y1 = t.z, b2x1 = t.w;

    // ---- GIoU (reference div_no_nan semantics) ----
    const float a1 = fmaxf(b1y1 - b1y0, 0.0f) * fmaxf(b1x1 - b1x0, 0.0f);
    const float a2 = fmaxf(b2y1 - b2y0, 0.0f) * fmaxf(b2x1 - b2x0, 0.0f);

    const float iy = fmaxf(fminf(b1y1, b2y1) - fmaxf(b1y0, b2y0), 0.0f);
    const float ix = fmaxf(fminf(b1x1, b2x1) - fmaxf(b1x0, b2x0), 0.0f);
    const float inter = iy * ix;
    const float uni   = a1 + a2 - inter;
    const float iou   = (uni != 0.0f) ? (inter / uni) : 0.0f;

    const float ey = fmaxf(fmaxf(b1y1, b2y1) - fminf(b1y0, b2y0), 0.0f);
    const float ex = fmaxf(fmaxf(b1x1, b2x1) - fminf(b1x0, b2x0), 0.0f);
    const float enc  = ey * ex;
    const float giou = iou - ((enc != 0.0f) ? ((enc - uni) / enc) : 0.0f);

    float loss = (1.0f - giou) * m;
    float mask = m;

    // ---- block reduction: 4 warps ----
    #pragma unroll
    for (int off = 16; off > 0; off >>= 1) {
        loss += __shfl_down_sync(0xFFFFFFFFu, loss, off);
        mask += __shfl_down_sync(0xFFFFFFFFu, mask, off);
    }
    __shared__ float s_loss[4], s_mask[4];
    const int lane = threadIdx.x & 31;
    const int warp = threadIdx.x >> 5;
    if (lane == 0) { s_loss[warp] = loss; s_mask[warp] = mask; }
    __syncthreads();

    // ---- tail: publish partial, ticket; last block reduces in parallel ----
    unsigned ticket = 0xFFFFFFFFu;
    if (threadIdx.x == 0) {
        const float bl = s_loss[0] + s_loss[1] + s_loss[2] + s_loss[3];
        const float bm = s_mask[0] + s_mask[1] + s_mask[2] + s_mask[3];
        g_part[blockIdx.x] = make_float2(bl, bm);   // plain store, no RMW
        __threadfence();                            // release partial
        ticket = atomicAdd(&g_done, 1u);
    }
    // warp 0 learns whether it is the finisher
    ticket = __shfl_sync(0xFFFFFFFFu, ticket, 0);
    if (warp == 0 && ticket == (unsigned)(NB - 1)) {
        __threadfence();                            // acquire all partials
        // 128 float2 partials = 32 lanes x one float4 (two blocks per lane)
        const float4 v = __ldcv(reinterpret_cast<const float4*>(g_part) + lane);
        float L = v.x + v.z;
        float M = v.y + v.w;
        #pragma unroll
        for (int off = 16; off > 0; off >>= 1) {
            L += __shfl_down_sync(0xFFFFFFFFu, L, off);
            M += __shfl_down_sync(0xFFFFFFFFu, M, off);
        }
        if (lane == 0) {
            *(volatile unsigned int*)&g_done = 0;   // reset for next replay
            out[0] = L / M;      // reference uses a plain divide here
        }
    }
}

extern "C" void kernel_launch(void* const* d_in, const int* in_sizes, int n_in,
                              void* d_out, int out_size)
{
    const float* loc_pred = (const float*)d_in[0];
    const float* loc_true = (const float*)d_in[1];
    const float* reg_mask = (const float*)d_in[2];
    const int*   indices  = (const int*)  d_in[3];
    float*       out      = (float*)d_out;
    (void)in_sizes; (void)n_in; (void)out_size;

    giou_loss_kernel<<<NB, NT>>>(loc_pred, loc_true, reg_mask, indices, out);
}

// round 9
// speedup vs baseline: 1.1055x; 1.0039x over previous
#include <cuda_runtime.h>
#include <cuda_bf16.h>

// Problem constants (fixed by the reference):
//   B=128, W=256, H=256, MAX_OBJS=128  -> 16384 boxes
// Inputs (metadata order):
//   d_in[0] loc_pred  f32 [128,256,256,4]
//   d_in[1] loc_true  f32 [128,128,4]
//   d_in[2] reg_mask  f32 [128,128]
//   d_in[3] indices   i32 [128,128,3]
// Output: f32 scalar.

#define NB 128   // blocks  (one wave; max per-SM memory-pipe parallelism)
#define NT 128   // threads

__device__ float        g_loss_sum = 0.0f;
__device__ float        g_mask_sum = 0.0f;
__device__ unsigned int g_done     = 0;

__global__ void __launch_bounds__(NT) giou_loss_kernel(
    const float* __restrict__ loc_pred,
    const float* __restrict__ loc_true,
    const float* __restrict__ reg_mask,
    const int*   __restrict__ indices,
    float*       __restrict__ out)
{
    const int i = blockIdx.x * NT + threadIdx.x;   // box index in [0, 16384)

    // ---- independent loads first (overlap DRAM latency) ----
    const int bidx = __ldg(indices + (size_t)i * 3 + 0);
    const int pos  = __ldg(indices + (size_t)i * 3 + 1);
    const float4 t = *reinterpret_cast<const float4*>(loc_true + (size_t)i * 4);
    const float  m = __ldg(reg_mask + i);

    // ---- dependent gather: predicted box, normalize by 256 ----
    const float4 p = *reinterpret_cast<const float4*>(
        loc_pred + (((size_t)bidx << 16) + (size_t)pos) * 4);
    const float inv = 1.0f / 256.0f;
    const float b1y0 = p.x * inv, b1x0 = p.y * inv;
    const float b1y1 = p.z * inv, b1x1 = p.w * inv;
    const float b2y0 = t.x, b2x0 = t.y, b2y1 = t.z, b2x1 = t.w;

    // ---- GIoU (reference div_no_nan semantics) ----
    const float a1 = fmaxf(b1y1 - b1y0, 0.0f) * fmaxf(b1x1 - b1x0, 0.0f);
    const float a2 = fmaxf(b2y1 - b2y0, 0.0f) * fmaxf(b2x1 - b2x0, 0.0f);

    const float iy = fmaxf(fminf(b1y1, b2y1) - fmaxf(b1y0, b2y0), 0.0f);
    const float ix = fmaxf(fminf(b1x1, b2x1) - fmaxf(b1x0, b2x0), 0.0f);
    const float inter = iy * ix;
    const float uni   = a1 + a2 - inter;
    const float iou   = (uni != 0.0f) ? (inter / uni) : 0.0f;

    const float ey = fmaxf(fmaxf(b1y1, b2y1) - fminf(b1y0, b2y0), 0.0f);
    const float ex = fmaxf(fmaxf(b1x1, b2x1) - fminf(b1x0, b2x0), 0.0f);
    const float enc  = ey * ex;
    const float giou = iou - ((enc != 0.0f) ? ((enc - uni) / enc) : 0.0f);

    float loss = (1.0f - giou) * m;
    float mask = m;

    // ---- block reduction: 4 warps ----
    #pragma unroll
    for (int off = 16; off > 0; off >>= 1) {
        loss += __shfl_down_sync(0xFFFFFFFFu, loss, off);
        mask += __shfl_down_sync(0xFFFFFFFFu, mask, off);
    }
    __shared__ float s_loss[4], s_mask[4];
    const int lane = threadIdx.x & 31;
    const int warp = threadIdx.x >> 5;
    if (lane == 0) { s_loss[warp] = loss; s_mask[warp] = mask; }
    __syncthreads();

    if (threadIdx.x == 0) {
        const float bl = s_loss[0] + s_loss[1] + s_loss[2] + s_loss[3];
        const float bm = s_mask[0] + s_mask[1] + s_mask[2] + s_mask[3];
        atomicAdd(&g_loss_sum, bl);
        atomicAdd(&g_mask_sum, bm);
        __threadfence();                          // release accumulator adds
        const unsigned ticket = atomicAdd(&g_done, 1u);
        if (ticket == (unsigned)(NB - 1)) {
            __threadfence();                      // acquire: all adds visible
            // Accumulators are FINAL here: read with two independent
            // volatile loads (one overlapped round-trip) instead of
            // three serial atomicExch RMWs.
            const float L = *(volatile float*)&g_loss_sum;
            const float M = *(volatile float*)&g_mask_sum;
            out[0] = L / M;                       // reference: plain divide
            // Reset for the next graph replay (stream-ordered: these
            // stores complete before the next replay launches).
            *(volatile float*)&g_loss_sum = 0.0f;
            *(volatile float*)&g_mask_sum = 0.0f;
            *(volatile unsigned int*)&g_done = 0u;
        }
    }
}

extern "C" void kernel_launch(void* const* d_in, const int* in_sizes, int n_in,
                              void* d_out, int out_size)
{
    const float* loc_pred = (const float*)d_in[0];
    const float* loc_true = (const float*)d_in[1];
    const float* reg_mask = (const float*)d_in[2];
    const int*   indices  = (const int*)  d_in[3];
    float*       out      = (float*)d_out;
    (void)in_sizes; (void)n_in; (void)out_size;

    giou_loss_kernel<<<NB, NT>>>(loc_pred, loc_true, reg_mask, indices, out);
}